// round 2
// baseline (speedup 1.0000x reference)
#include <cuda_runtime.h>
#include <math.h>

#define WW 512
#define HH 512
#define NT 180
#define NR 725

// Scratch: transposed image so the y-sweep branch gathers row-wise too.
__device__ float g_imgT[WW * HH];
// Per-theta precomputed constants (computed once per launch, deterministic).
__device__ float g_coef[NT];
__device__ float g_denom[NT];
__device__ float g_rcp[NT];
__device__ int   g_usex[NT];

__global__ void init_theta_kernel() {
    int t = blockIdx.x * blockDim.x + threadIdx.x;
    if (t >= NT) return;
    // theta = f32(t) * f32(pi/180), matching jnp (x64 disabled -> all f32)
    float theta = __fmul_rn((float)t, (float)(M_PI / 180.0));
    // Trig in double, rounded to f32: within ~1 ulp of libdevice __nv_cosf/__nv_sinf
    float c = (float)cos((double)theta);
    float s = (float)sin((double)theta);
    int ux = (fabsf(s) >= fabsf(c)) ? 1 : 0;   // reference: use_x = |sin| >= |cos|
    float coef = ux ? c : s;
    float den  = ux ? s : c;   // |den| >= 0.707 in the selected branch; EPS guard moot
    g_coef[t]  = coef;
    g_denom[t] = den;
    g_rcp[t]   = __frcp_rn(den);   // correctly-rounded reciprocal for Markstein div
    g_usex[t]  = ux;
}

__global__ void transpose_kernel(const float* __restrict__ in) {
    __shared__ float tile[32][33];
    int x  = blockIdx.x * 32 + threadIdx.x;
    int y0 = blockIdx.y * 32;
    #pragma unroll
    for (int j = threadIdx.y; j < 32; j += 8)
        tile[j][threadIdx.x] = in[(y0 + j) * WW + x];
    __syncthreads();
    int xo  = y0 + threadIdx.x;
    int yo0 = blockIdx.x * 32;
    #pragma unroll
    for (int j = threadIdx.y; j < 32; j += 8)
        g_imgT[(yo0 + j) * WW + xo] = tile[threadIdx.x][j];
}

__global__ __launch_bounds__(128)
void hough_kernel(const float* __restrict__ img, float* __restrict__ out) {
    const int t = blockIdx.y;
    const int r = blockIdx.x * 128 + threadIdx.x;

    const float coef = g_coef[t];
    const float den  = g_denom[t];
    const float rcp  = g_rcp[t];
    const float* __restrict__ base = g_usex[t] ? img : g_imgT;

    // rhos = linspace(-diag, diag, 725) in f32, matching jnp order of ops
    const float diag = sqrtf((float)(WW * WW + HH * HH));
    const float step = __fdiv_rn(__fadd_rn(diag, diag), (float)(NR - 1));
    const float rho  = __fadd_rn(-diag, __fmul_rn(step, (float)r));

    // ---- per-thread valid-n window (double, generous slack; the in-bounds
    //      predicate below is ground truth, so the window only needs to be
    //      a superset of the valid range) ----
    int n0 = WW, n1 = -1;
    if (r < NR) {
        double cd = (double)coef, dd = (double)den, Rd = (double)rho;
        if (fabs(cd) > 1e-7) {
            double na = (Rd + 0.55 * dd) / cd;      // y = -0.55 boundary
            double nb = (Rd - 511.55 * dd) / cd;    // y = 511.55 boundary
            double lo = fmin(na, nb), hi = fmax(na, nb);
            if (!(hi < -0.5 || lo > (double)WW - 0.5)) {
                int a = (int)floor(lo) - 1;
                int b = (int)ceil(hi) + 1;
                n0 = a > 0 ? a : 0;
                n1 = b < (WW - 1) ? b : (WW - 1);
            }
        } else {
            double y0 = Rd / dd;                    // slope ~0: all-or-nothing
            if (y0 > -1.5 && y0 < 512.5) { n0 = 0; n1 = WW - 1; }
        }
    }
    // Warp-uniform range so the gather stays coalesced (lanes = adjacent rho)
    const int nb = (int)__reduce_min_sync(0xffffffffu, (unsigned)n0);
    const int ne = (int)__reduce_max_sync(0xffffffffu, (unsigned)(n1 + 1));

    // Dual accumulators: halve the loop-carried FADD chain.
    float acc0 = 0.0f, acc1 = 0.0f;
    const float negd = -den;
    float nf0 = (float)nb;
    float nf1 = (float)nb + 1.0f;
    int n = nb;
    #pragma unroll 2
    for (; n + 1 < ne; n += 2) {
        // Bit-exact replica of reference f32 math:
        //   y_f = fl(fl(rho - fl(n*coef)) / den), via Markstein correctly-rounded div
        float t1a = __fmul_rn(nf0, coef);
        float xa  = __fsub_rn(rho, t1a);
        float q0a = __fmul_rn(xa, rcp);
        float ea  = __fmaf_rn(negd, q0a, xa);
        float qa  = __fmaf_rn(rcp, ea, q0a);        // == __fdiv_rn(xa, den)
        int   ya  = __float2int_rn(qa);             // round-half-even == jnp.round

        float t1b = __fmul_rn(nf1, coef);
        float xb  = __fsub_rn(rho, t1b);
        float q0b = __fmul_rn(xb, rcp);
        float eb  = __fmaf_rn(negd, q0b, xb);
        float qb  = __fmaf_rn(rcp, eb, q0b);
        int   yb  = __float2int_rn(qb);

        if ((unsigned)ya < (unsigned)HH) acc0 += __ldg(base + n * WW + ya);
        if ((unsigned)yb < (unsigned)HH) acc1 += __ldg(base + (n + 1) * WW + yb);
        nf0 += 2.0f;
        nf1 += 2.0f;
    }
    if (n < ne) {
        float t1 = __fmul_rn(nf0, coef);
        float x  = __fsub_rn(rho, t1);
        float q0 = __fmul_rn(x, rcp);
        float e  = __fmaf_rn(negd, q0, x);
        float q  = __fmaf_rn(rcp, e, q0);
        int   yi = __float2int_rn(q);
        if ((unsigned)yi < (unsigned)HH) acc0 += __ldg(base + n * WW + yi);
    }

    if (r < NR) out[r * NT + t] = acc0 + acc1;
}

extern "C" void kernel_launch(void* const* d_in, const int* in_sizes, int n_in,
                              void* d_out, int out_size) {
    const float* img = (const float*)d_in[0];
    float* out = (float*)d_out;
    (void)in_sizes; (void)n_in; (void)out_size;

    init_theta_kernel<<<1, 192>>>();
    transpose_kernel<<<dim3(WW / 32, HH / 32), dim3(32, 8)>>>(img);
    hough_kernel<<<dim3((NR + 127) / 128, NT), 128>>>(img, out);
}

// round 11
// speedup vs baseline: 1.1479x; 1.1479x over previous
#include <cuda_runtime.h>
#include <cuda_fp16.h>
#include <math.h>

#define WW 512
#define HH 512
#define NT 180
#define NR 725

// Half-precision copies of the image: same layout (x-sweep) and transposed
// (y-sweep) so both branches gather row-wise with small per-warp spans.
__device__ __half g_imgH[WW * HH];
__device__ __half g_imgTH[WW * HH];

// One pass over the f32 image: emit half copy + half transpose.
__global__ void prep_kernel(const float* __restrict__ in) {
    __shared__ float tile[32][33];
    int x  = blockIdx.x * 32 + threadIdx.x;
    int y0 = blockIdx.y * 32;
    #pragma unroll
    for (int j = threadIdx.y; j < 32; j += 8) {
        float v = in[(y0 + j) * WW + x];
        tile[j][threadIdx.x] = v;
        g_imgH[(y0 + j) * WW + x] = __float2half_rn(v);   // coalesced copy
    }
    __syncthreads();
    int xo  = y0 + threadIdx.x;
    int yo0 = blockIdx.x * 32;
    #pragma unroll
    for (int j = threadIdx.y; j < 32; j += 8)
        g_imgTH[(yo0 + j) * WW + xo] = __float2half_rn(tile[threadIdx.x][j]);
}

// One sample of the bit-exact reference index math:
//   y = round_half_even( fl(fl(rho - fl(nf*coef)) / den) )
// div replicated via Markstein sequence with correctly-rounded rcp.
__device__ __forceinline__ void dht_sample(
    float nf, float rho, float coef, float rcp, float negd,
    const __half* __restrict__ base, int n, float& acc)
{
    float t1 = __fmul_rn(nf, coef);
    float x  = __fsub_rn(rho, t1);
    float q0 = __fmul_rn(x, rcp);
    float e  = __fmaf_rn(negd, q0, x);
    float q  = __fmaf_rn(rcp, e, q0);         // == __fdiv_rn(x, den)
    int   yi = __float2int_rn(q);             // round-half-even == jnp.round
    if ((unsigned)yi < (unsigned)HH)
        acc += __half2float(__ldg(base + n * WW + yi));
}

__global__ __launch_bounds__(128)
void hough_kernel(float* __restrict__ out) {
    const int t = blockIdx.y;
    const int r = blockIdx.x * 128 + threadIdx.x;

    // Per-block theta constants: one thread does double trig, smem broadcast.
    __shared__ float s_coef, s_den, s_rcp;
    __shared__ int   s_usex;
    if (threadIdx.x == 0) {
        // theta = f32(t) * f32(pi/180), matching jnp (all-f32 trace)
        float theta = __fmul_rn((float)t, (float)(M_PI / 180.0));
        // trig in double rounded to f32: within ~1 ulp of libdevice
        float c = (float)cos((double)theta);
        float s = (float)sin((double)theta);
        int ux = (fabsf(s) >= fabsf(c)) ? 1 : 0;   // use_x = |sin| >= |cos|
        s_coef = ux ? c : s;
        s_den  = ux ? s : c;      // |den| >= 0.707 in selected branch
        s_rcp  = __frcp_rn(ux ? s : c);
        s_usex = ux;
    }
    __syncthreads();
    const float coef = s_coef;
    const float den  = s_den;
    const float rcp  = s_rcp;
    const __half* __restrict__ base = s_usex ? g_imgH : g_imgTH;

    // rhos = linspace(-diag, diag, 725) in f32, matching jnp order of ops
    const float diag = sqrtf((float)(WW * WW + HH * HH));
    const float step = __fdiv_rn(__fadd_rn(diag, diag), (float)(NR - 1));
    const float rho  = __fadd_rn(-diag, __fmul_rn(step, (float)r));

    // ---- valid-n window, f32 with generous slack. The in-bounds predicate
    //      in the loop is ground truth; this only needs to be a superset. ----
    int n0 = WW, n1 = -1;
    if (r < NR) {
        if (fabsf(coef) > 1e-6f) {
            float ic = __frcp_rn(coef);
            float na = (rho + 0.6f * den) * ic;       // y = -0.6 boundary
            float nb = (rho - 511.6f * den) * ic;     // y = 511.6 boundary
            float lo = fminf(na, nb), hi = fmaxf(na, nb);
            if (!(hi < -0.5f || lo > (float)WW - 0.5f)) {
                int a = (int)floorf(lo) - 2;
                int b = (int)ceilf(hi) + 2;
                n0 = a > 0 ? a : 0;
                n1 = b < (WW - 1) ? b : (WW - 1);
            }
        } else {
            float y0 = rho * rcp;                     // slope ~0: all-or-nothing
            if (y0 > -1.5f && y0 < 512.5f) { n0 = 0; n1 = WW - 1; }
        }
    }
    // Warp-uniform range so the gather stays coalesced (lanes = adjacent rho)
    const int nb = (int)__reduce_min_sync(0xffffffffu, (unsigned)n0);
    const int ne = (int)__reduce_max_sync(0xffffffffu, (unsigned)(n1 + 1));

    // 8 accumulators: MLP=8 per warp to cover L2 hit latency (234-262 cyc)
    // with slack; independent partial sums, pure reassociation.
    float acc0 = 0.0f, acc1 = 0.0f, acc2 = 0.0f, acc3 = 0.0f;
    float acc4 = 0.0f, acc5 = 0.0f, acc6 = 0.0f, acc7 = 0.0f;
    const float negd = -den;
    float nf = (float)nb;
    int n = nb;
    for (; n + 7 < ne; n += 8) {
        dht_sample(nf,        rho, coef, rcp, negd, base, n,     acc0);
        dht_sample(nf + 1.0f, rho, coef, rcp, negd, base, n + 1, acc1);
        dht_sample(nf + 2.0f, rho, coef, rcp, negd, base, n + 2, acc2);
        dht_sample(nf + 3.0f, rho, coef, rcp, negd, base, n + 3, acc3);
        dht_sample(nf + 4.0f, rho, coef, rcp, negd, base, n + 4, acc4);
        dht_sample(nf + 5.0f, rho, coef, rcp, negd, base, n + 5, acc5);
        dht_sample(nf + 6.0f, rho, coef, rcp, negd, base, n + 6, acc6);
        dht_sample(nf + 7.0f, rho, coef, rcp, negd, base, n + 7, acc7);
        nf += 8.0f;
    }
    for (; n < ne; ++n) {
        dht_sample(nf, rho, coef, rcp, negd, base, n, acc0);
        nf += 1.0f;
    }

    if (r < NR)
        out[r * NT + t] = ((acc0 + acc1) + (acc2 + acc3))
                        + ((acc4 + acc5) + (acc6 + acc7));
}

extern "C" void kernel_launch(void* const* d_in, const int* in_sizes, int n_in,
                              void* d_out, int out_size) {
    const float* img = (const float*)d_in[0];
    float* out = (float*)d_out;
    (void)in_sizes; (void)n_in; (void)out_size;

    prep_kernel<<<dim3(WW / 32, HH / 32), dim3(32, 8)>>>(img);
    hough_kernel<<<dim3((NR + 127) / 128, NT), 128>>>(out);
}